// round 9
// baseline (speedup 1.0000x reference)
#include <cuda_runtime.h>

static constexpr int B = 4096;
static constexpr int K = 1024;
static constexpr int C = 10;
static constexpr int M = 19;

// Accum kernel: block = 32 b x 256 k, 256 threads.
// Thread = (bg 0..7, kc 0..31): owns 4 consecutive b (int4 loads) and 8 k.
// Warp k-row load: 8 lanes x 16B = 128B = FULL line -> 4x bytes per L1tex
// queue entry vs the 32B/line pattern of all previous rounds.
static constexpr int NB      = 32;
static constexpr int NKC     = 32;              // k-chunks per block
static constexpr int THREADS = 8 * NKC;         // 256
static constexpr int KSPLIT  = 4;
static constexpr int KBLK    = K / KSPLIT;      // 256
static constexpr int KCHUNK  = KBLK / NKC;      // 8 iterations (32 samples/thread)

static constexpr int BSTR    = THREADS + 1;     // 257: bank = (row + tid) % 32

// Dynamic smem layout (floats):
//  [0 , 4*19*257)            bins   : [l][m][tid]
//  [BINS, BINS + 4*100*8)    table  : [l][ij][bg]
static constexpr int BINS_F  = 4 * M * BSTR;          // 19532
static constexpr int TBL_F   = 4 * 100 * 8;           // 3200
static constexpr int SMEM_B  = (BINS_F + TBL_F) * 4;  // ~90.9 KB

__device__ float g_scratch[B * M];   // zero-init; re-zeroed by norm kernel

__global__ __launch_bounds__(THREADS, 2)
void ised_accum(const float* __restrict__ x1,
                const float* __restrict__ x2,
                const int*   __restrict__ idx1,
                const int*   __restrict__ idx2)
{
    extern __shared__ float sm[];
    float* __restrict__ bins  = sm;            // [l*M + m][tid] stride BSTR
    float* __restrict__ table = sm + BINS_F;   // [l][ij][bg]

    const int tid = threadIdx.x;
    const int b0  = blockIdx.x * NB;
    const int k0  = blockIdx.y * KBLK;

    // ---- Tables: table[l*800 + ij*8 + bg] = x1[b0+bg*4+l, i] * x2[..., j] ----
    for (int e = tid; e < 4 * 100 * 8; e += THREADS) {
        const int bg = e & 7;
        const int ij = (e >> 3) % 100;
        const int l  = e / 800;
        const int i  = ij / 10;
        const int j  = ij - i * 10;
        const int b  = b0 + bg * 4 + l;
        table[e] = __ldg(&x1[b * C + i]) * __ldg(&x2[b * C + j]);
    }
    for (int e = tid; e < BINS_F; e += THREADS) {
        bins[e] = 0.0f;
    }
    __syncthreads();

    // ---- Main loop: int4 pair per iter -> 4 samples ----
    const int bg = tid & 7;
    const int kc = tid >> 3;
    const int b  = b0 + bg * 4;                 // 16B aligned

    const int4* __restrict__ p1 =
        (const int4*)(idx1 + (size_t)(k0 + kc * KCHUNK) * B + b);
    const int4* __restrict__ p2 =
        (const int4*)(idx2 + (size_t)(k0 + kc * KCHUNK) * B + b);

    #pragma unroll
    for (int k = 0; k < KCHUNK; k++) {
        const int4 a = __ldg(&p1[(size_t)k * (B / 4)]);
        const int4 c = __ldg(&p2[(size_t)k * (B / 4)]);
        // 4 independent b-lanes, each with its own table slice & bin rows
        bins[(0 * M + a.x + c.x) * BSTR + tid] += table[0 * 800 + (a.x * 10 + c.x) * 8 + bg];
        bins[(1 * M + a.y + c.y) * BSTR + tid] += table[1 * 800 + (a.y * 10 + c.y) * 8 + bg];
        bins[(2 * M + a.z + c.z) * BSTR + tid] += table[2 * 800 + (a.z * 10 + c.z) * 8 + bg];
        bins[(3 * M + a.w + c.w) * BSTR + tid] += table[3 * 800 + (a.w * 10 + c.w) * 8 + bg];
    }
    __syncthreads();

    // ---- Reduce 32 kc-partials per (bg, l, m); atomicAdd to scratch ----
    // 32 b * 19 m = 608 entries
    for (int e = tid; e < NB * M; e += THREADS) {
        const int bl = e % NB;                  // b within block
        const int m  = e / NB;
        const int bg2 = bl >> 2;
        const int l   = bl & 3;
        float v = 0.0f;
        #pragma unroll
        for (int c2 = 0; c2 < NKC; c2++) {
            v += bins[(l * M + m) * BSTR + c2 * 8 + bg2];
        }
        atomicAdd(&g_scratch[(b0 + bl) * M + m], v);
    }
}

// Norm kernel: normalize rows, write out, re-zero scratch.
static constexpr int NB2 = 16;
__global__ __launch_bounds__(128)
void ised_norm(float* __restrict__ out)
{
    __shared__ float s[NB2][M + 1];

    const int tid = threadIdx.x;
    const int r0  = blockIdx.x * NB2;

    for (int e = tid; e < NB2 * M; e += 128) {
        const int bl = e / M;
        const int m  = e - bl * M;
        const int gi = (r0 + bl) * M + m;
        s[bl][m] = g_scratch[gi];
        g_scratch[gi] = 0.0f;
    }
    __syncthreads();

    if (tid < NB2) {
        float sq = 0.0f;
        #pragma unroll
        for (int m = 0; m < M; m++) {
            const float v = s[tid][m];
            sq += v * v;
        }
        s[tid][M] = 1.0f / fmaxf(sqrtf(sq), 1e-12f);
    }
    __syncthreads();

    for (int e = tid; e < NB2 * M; e += 128) {
        const int bl = e / M;
        const int m  = e - bl * M;
        out[(size_t)(r0 + bl) * M + m] = s[bl][m] * s[bl][M];
    }
}

extern "C" void kernel_launch(void* const* d_in, const int* in_sizes, int n_in,
                              void* d_out, int out_size)
{
    const float* x1   = (const float*)d_in[0];   // [B, C]
    const float* x2   = (const float*)d_in[1];   // [B, C]
    const int*   idx1 = (const int*)d_in[2];     // [K, B]
    const int*   idx2 = (const int*)d_in[3];     // [K, B]
    float*       out  = (float*)d_out;           // [B, M]

    (void)in_sizes; (void)n_in; (void)out_size;

    // Unconditional (no static guard; idempotent, deterministic, capture-safe).
    cudaFuncSetAttribute(ised_accum,
                         cudaFuncAttributeMaxDynamicSharedMemorySize, SMEM_B);

    dim3 grid(B / NB, KSPLIT);
    ised_accum<<<grid, THREADS, SMEM_B>>>(x1, x2, idx1, idx2);
    ised_norm<<<B / NB2, 128>>>(out);
}

// round 10
// speedup vs baseline: 1.2534x; 1.2534x over previous
#include <cuda_runtime.h>

static constexpr int B = 4096;
static constexpr int K = 1024;
static constexpr int C = 10;
static constexpr int M = 19;

// Block = 32 b x 512 k, 256 threads. Thread = (bg 0..7, kc 0..31):
// owns 4 consecutive b (int4 loads). Warp k-row = 8 lanes x 16B = 128B FULL line.
static constexpr int NB      = 32;
static constexpr int NKC     = 32;
static constexpr int THREADS = 8 * NKC;         // 256
static constexpr int KSPLIT  = 2;
static constexpr int KBLK    = K / KSPLIT;      // 512
static constexpr int KCHUNK  = KBLK / NKC;      // 16 iterations (64 samples/thread)

static constexpr int BSTR    = THREADS + 1;     // 257 -> bank=(row+tid)%32, conflict-free

static constexpr int BINS_F  = 4 * M * BSTR;          // 19532 floats (78.1KB)
static constexpr int TBL_F   = 4 * 100 * 8;           // 3200 floats  (12.8KB)
static constexpr int SMEM_B  = (BINS_F + TBL_F) * 4;  // 90928 B

__device__ float g_scratch[B * M];     // zero-init; re-zeroed by finishing block
__device__ int   g_ticket[B / NB];     // zero-init; reset by finishing block

__global__ __launch_bounds__(THREADS, 2)
void ised_kernel(const float* __restrict__ x1,
                 const float* __restrict__ x2,
                 const int*   __restrict__ idx1,
                 const int*   __restrict__ idx2,
                 float*       __restrict__ out)
{
    extern __shared__ float sm[];
    float* __restrict__ bins  = sm;            // [(l*M + o)][tid], stride BSTR
    float* __restrict__ table = sm + BINS_F;   // [l][ij][bg]
    __shared__ float rowsum[NB][M + 1];
    __shared__ int   s_last;

    const int tid = threadIdx.x;
    const int b0  = blockIdx.x * NB;
    const int k0  = blockIdx.y * KBLK;

    // ---- Tables: table[l*800 + ij*8 + bg] = x1[b0+bg*4+l, i] * x2[..., j] ----
    for (int e = tid; e < 4 * 100 * 8; e += THREADS) {
        const int bg = e & 7;
        const int ij = (e >> 3) % 100;
        const int l  = e / 800;
        const int i  = ij / 10;
        const int j  = ij - i * 10;
        const int b  = b0 + bg * 4 + l;
        table[e] = __ldg(&x1[b * C + i]) * __ldg(&x2[b * C + j]);
    }
    for (int e = tid; e < BINS_F; e += THREADS) {
        bins[e] = 0.0f;
    }
    __syncthreads();

    // ---- Main loop: two int4 loads -> 4 samples/iter, full-line fetches ----
    const int bg = tid & 7;
    const int kc = tid >> 3;
    const int b  = b0 + bg * 4;                 // 16B aligned

    const int4* __restrict__ p1 =
        (const int4*)(idx1 + (size_t)(k0 + kc * KCHUNK) * B + b);
    const int4* __restrict__ p2 =
        (const int4*)(idx2 + (size_t)(k0 + kc * KCHUNK) * B + b);

    #pragma unroll 4
    for (int k = 0; k < KCHUNK; k++) {
        const int4 a = __ldg(&p1[(size_t)k * (B / 4)]);
        const int4 c = __ldg(&p2[(size_t)k * (B / 4)]);
        bins[(0 * M + a.x + c.x) * BSTR + tid] += table[0 * 800 + (a.x * 10 + c.x) * 8 + bg];
        bins[(1 * M + a.y + c.y) * BSTR + tid] += table[1 * 800 + (a.y * 10 + c.y) * 8 + bg];
        bins[(2 * M + a.z + c.z) * BSTR + tid] += table[2 * 800 + (a.z * 10 + c.z) * 8 + bg];
        bins[(3 * M + a.w + c.w) * BSTR + tid] += table[3 * 800 + (a.w * 10 + c.w) * 8 + bg];
    }
    __syncthreads();

    // ---- Reduce 32 kc-partials per (b, m); push to L2 scratch ----
    for (int e = tid; e < NB * M; e += THREADS) {
        const int bl  = e % NB;
        const int m   = e / NB;
        const int bg2 = bl >> 2;
        const int l   = bl & 3;
        float v = 0.0f;
        #pragma unroll
        for (int c2 = 0; c2 < NKC; c2++) {
            v += bins[(l * M + m) * BSTR + c2 * 8 + bg2];
        }
        atomicAdd(&g_scratch[(b0 + bl) * M + m], v);
    }

    // ---- Ticket: last KSPLIT-block for this row-group finishes the rows ----
    __threadfence();
    __syncthreads();
    if (tid == 0) {
        s_last = (atomicAdd(&g_ticket[blockIdx.x], 1) == KSPLIT - 1);
    }
    __syncthreads();
    if (!s_last) return;

    for (int e = tid; e < NB * M; e += THREADS) {
        const int bl = e % NB;
        const int m  = e / NB;
        rowsum[bl][m] = __ldcg(&g_scratch[(b0 + bl) * M + m]);
    }
    __syncthreads();

    if (tid < NB) {
        float sq = 0.0f;
        #pragma unroll
        for (int m = 0; m < M; m++) {
            const float v = rowsum[tid][m];
            sq += v * v;
        }
        rowsum[tid][M] = 1.0f / fmaxf(sqrtf(sq), 1e-12f);
    }
    __syncthreads();

    for (int e = tid; e < NB * M; e += THREADS) {
        const int bl = e % NB;
        const int m  = e / NB;
        out[(size_t)(b0 + bl) * M + m] = rowsum[bl][m] * rowsum[bl][M];
        __stcg(&g_scratch[(b0 + bl) * M + m], 0.0f);   // reset for next replay
    }
    if (tid == 0) {
        g_ticket[blockIdx.x] = 0;
    }
}

extern "C" void kernel_launch(void* const* d_in, const int* in_sizes, int n_in,
                              void* d_out, int out_size)
{
    const float* x1   = (const float*)d_in[0];   // [B, C]
    const float* x2   = (const float*)d_in[1];   // [B, C]
    const int*   idx1 = (const int*)d_in[2];     // [K, B]
    const int*   idx2 = (const int*)d_in[3];     // [K, B]
    float*       out  = (float*)d_out;           // [B, M]

    (void)in_sizes; (void)n_in; (void)out_size;

    cudaFuncSetAttribute(ised_kernel,
                         cudaFuncAttributeMaxDynamicSharedMemorySize, SMEM_B);

    dim3 grid(B / NB, KSPLIT);
    ised_kernel<<<grid, THREADS, SMEM_B>>>(x1, x2, idx1, idx2, out);
}